// round 6
// baseline (speedup 1.0000x reference)
#include <cuda_runtime.h>

// Problem constants
#define Bsz 512
#define Tn  2048
#define Dn  64
#define Hn  66
#define Gn  264          // 4*H
#define RPB 4            // batch rows per block
#define NBLK (Bsz / RPB) // 128
#define NTHR Gn          // 264 threads: 1 per gate output == 4 rows x 66 feats
#define WPITCH 68        // padded row stride (floats): 68*4B = 272B = 17*16B -> conflict-free LDS.128

typedef unsigned long long ull;

// Scratch for h_T (final hidden state), consumed by the BN+FC kernel
__device__ float g_hT[Bsz * Hn];

// ---- packed f32x2 helpers (Blackwell) ----
__device__ __forceinline__ ull fma2(ull a, ull b, ull c) {
    ull d;
    asm("fma.rn.f32x2 %0, %1, %2, %3;" : "=l"(d) : "l"(a), "l"(b), "l"(c));
    return d;
}
__device__ __forceinline__ float hadd2(ull a) {
    float x, y;
    asm("mov.b64 {%0, %1}, %2;" : "=f"(x), "=f"(y) : "l"(a));
    return x + y;
}

__device__ __forceinline__ float sigf(float x) {
    return 1.0f / (1.0f + __expf(-x));
}
__device__ __forceinline__ float tanh_fast(float x) {
    float e = __expf(-2.0f * fabsf(x));
    float r = (1.0f - e) / (1.0f + e);
    return copysignf(r, x);
}

extern __shared__ float smem[];

__global__ void __launch_bounds__(NTHR, 1) lstm_kernel(
    const float* __restrict__ x,      // [B, T, D]
    const float* __restrict__ W_ih,   // [4H, D]
    const float* __restrict__ W_hh,   // [4H, H]
    const float* __restrict__ b_ih,   // [4H]
    const float* __restrict__ b_hh)   // [4H]
{
    // SMEM layout (floats)
    float* Wih_s   = smem;                         // Gn * WPITCH
    float* Whh_s   = Wih_s + Gn * WPITCH;          // Gn * WPITCH
    float* bias_s  = Whh_s + Gn * WPITCH;          // Gn
    float* h_s     = bias_s + Gn;                  // RPB * WPITCH
    float* x_s     = h_s + RPB * WPITCH;           // 2 * RPB * Dn (double buffered)
    float* gates_s = x_s + 2 * RPB * Dn;           // RPB * Gn

    const int tid  = threadIdx.x;
    const int row0 = blockIdx.x * RPB;

    // ---- load weights into padded SMEM (coalesced global reads) ----
    for (int i = tid; i < Gn * Dn; i += NTHR) {
        int r = i >> 6, c = i & 63;
        Wih_s[r * WPITCH + c] = W_ih[i];
    }
    for (int i = tid; i < Gn * Hn; i += NTHR) {
        int r = i / Hn, c = i - r * Hn;
        Whh_s[r * WPITCH + c] = W_hh[i];
    }
    for (int i = tid; i < Gn; i += NTHR) bias_s[i] = b_ih[i] + b_hh[i];
    for (int i = tid; i < RPB * WPITCH; i += NTHR) h_s[i] = 0.0f;

    // ---- preload x for t=0 ----
    const int r_l = tid >> 6;   // loader row 0..3
    const int d_l = tid & 63;   // loader dim 0..63
    if (tid < RPB * Dn) {
        x_s[r_l * Dn + d_l] = x[(row0 + r_l) * (Tn * Dn) + d_l];
    }
    __syncthreads();

    // update-phase mapping: thread -> (row, feature)
    const int ur = tid / Hn;        // 0..3
    const int uj = tid - ur * Hn;   // 0..65
    float c_st  = 0.0f;
    float h_last = 0.0f;

    const float* Wi = Wih_s + tid * WPITCH;
    const float* Wh = Whh_s + tid * WPITCH;
    const float  bz = bias_s[tid];

    int buf = 0;
    for (int t = 0; t < Tn; ++t) {
        // prefetch x for t+1 (latency hidden under the ~1100-cycle gate loop)
        float xv = 0.0f;
        if (tid < RPB * Dn && t + 1 < Tn) {
            xv = x[(row0 + r_l) * (Tn * Dn) + (t + 1) * Dn + d_l];
        }

        const float* xb = x_s + buf * (RPB * Dn);
        ull a0 = 0ull, a1 = 0ull, a2 = 0ull, a3 = 0ull;  // packed {0,0}

        // input projection: gates += x_t @ W_ih^T   (K packed in pairs)
        #pragma unroll
        for (int d = 0; d < Dn; d += 4) {
            ulonglong2 w  = *(const ulonglong2*)(Wi + d);
            ulonglong2 v0 = *(const ulonglong2*)(xb + 0 * Dn + d);
            ulonglong2 v1 = *(const ulonglong2*)(xb + 1 * Dn + d);
            ulonglong2 v2 = *(const ulonglong2*)(xb + 2 * Dn + d);
            ulonglong2 v3 = *(const ulonglong2*)(xb + 3 * Dn + d);
            a0 = fma2(w.x, v0.x, a0); a0 = fma2(w.y, v0.y, a0);
            a1 = fma2(w.x, v1.x, a1); a1 = fma2(w.y, v1.y, a1);
            a2 = fma2(w.x, v2.x, a2); a2 = fma2(w.y, v2.y, a2);
            a3 = fma2(w.x, v3.x, a3); a3 = fma2(w.y, v3.y, a3);
        }
        // recurrent projection: gates += h @ W_hh^T (k = 0..63 in float4 chunks)
        #pragma unroll
        for (int k = 0; k < 64; k += 4) {
            ulonglong2 w  = *(const ulonglong2*)(Wh + k);
            ulonglong2 v0 = *(const ulonglong2*)(h_s + 0 * WPITCH + k);
            ulonglong2 v1 = *(const ulonglong2*)(h_s + 1 * WPITCH + k);
            ulonglong2 v2 = *(const ulonglong2*)(h_s + 2 * WPITCH + k);
            ulonglong2 v3 = *(const ulonglong2*)(h_s + 3 * WPITCH + k);
            a0 = fma2(w.x, v0.x, a0); a0 = fma2(w.y, v0.y, a0);
            a1 = fma2(w.x, v1.x, a1); a1 = fma2(w.y, v1.y, a1);
            a2 = fma2(w.x, v2.x, a2); a2 = fma2(w.y, v2.y, a2);
            a3 = fma2(w.x, v3.x, a3); a3 = fma2(w.y, v3.y, a3);
        }
        {   // remainder k = 64, 65 (one packed pair)
            ull w  = *(const ull*)(Wh + 64);
            ull v0 = *(const ull*)(h_s + 0 * WPITCH + 64);
            ull v1 = *(const ull*)(h_s + 1 * WPITCH + 64);
            ull v2 = *(const ull*)(h_s + 2 * WPITCH + 64);
            ull v3 = *(const ull*)(h_s + 3 * WPITCH + 64);
            a0 = fma2(w, v0, a0);
            a1 = fma2(w, v1, a1);
            a2 = fma2(w, v2, a2);
            a3 = fma2(w, v3, a3);
        }

        gates_s[0 * Gn + tid] = hadd2(a0) + bz;
        gates_s[1 * Gn + tid] = hadd2(a1) + bz;
        gates_s[2 * Gn + tid] = hadd2(a2) + bz;
        gates_s[3 * Gn + tid] = hadd2(a3) + bz;
        __syncthreads();

        // stash prefetched x into the other buffer
        if (tid < RPB * Dn) {
            x_s[(buf ^ 1) * (RPB * Dn) + r_l * Dn + d_l] = xv;
        }

        // pointwise LSTM cell update (c kept in this thread's register forever)
        float gi = sigf(gates_s[ur * Gn + uj]);
        float gf = sigf(gates_s[ur * Gn + Hn + uj]);
        float gg = tanh_fast(gates_s[ur * Gn + 2 * Hn + uj]);
        float go = sigf(gates_s[ur * Gn + 3 * Hn + uj]);
        c_st   = gf * c_st + gi * gg;
        h_last = go * tanh_fast(c_st);
        h_s[ur * WPITCH + uj] = h_last;

        buf ^= 1;
        __syncthreads();
    }

    g_hT[(row0 + ur) * Hn + uj] = h_last;
}

// BatchNorm (batch stats) + fused final linear.
// logits[b] = const + sum_j hT[b][j] * w'[j]
//   w'[j]  = gamma[j] * rsqrt(var[j]+eps) * fc_w[j]
//   const  = fc_b + sum_j (beta[j] - mean[j]*rsqrt*gamma[j]) * fc_w[j]
__global__ void bn_fc_kernel(
    const float* __restrict__ gamma,
    const float* __restrict__ beta,
    const float* __restrict__ fcw,
    const float* __restrict__ fcb,
    float* __restrict__ out)
{
    __shared__ float wp_s[Hn];
    __shared__ float pc_s[Hn];
    __shared__ float cconst;
    const int tid = threadIdx.x;

    if (tid < Hn) {
        float s = 0.0f, sq = 0.0f;
        #pragma unroll 8
        for (int b = 0; b < Bsz; ++b) {
            float v = g_hT[b * Hn + tid];
            s += v; sq += v * v;
        }
        float mean = s * (1.0f / Bsz);
        float var  = sq * (1.0f / Bsz) - mean * mean;   // biased, matches jnp.var
        float rs   = rsqrtf(var + 1e-5f);
        float w    = gamma[tid] * rs * fcw[tid];
        wp_s[tid]  = w;
        pc_s[tid]  = beta[tid] * fcw[tid] - mean * w;
    }
    __syncthreads();
    if (tid == 0) {
        float s = fcb[0];
        for (int j = 0; j < Hn; ++j) s += pc_s[j];
        cconst = s;
    }
    __syncthreads();
    if (tid < Bsz) {
        float acc = cconst;
        #pragma unroll
        for (int j = 0; j < Hn; ++j) acc += g_hT[tid * Hn + j] * wp_s[j];
        out[tid] = acc;
    }
}

extern "C" void kernel_launch(void* const* d_in, const int* in_sizes, int n_in,
                              void* d_out, int out_size)
{
    const float* x     = (const float*)d_in[0];
    const float* W_ih  = (const float*)d_in[1];
    const float* W_hh  = (const float*)d_in[2];
    const float* b_ih  = (const float*)d_in[3];
    const float* b_hh  = (const float*)d_in[4];
    const float* gamma = (const float*)d_in[5];
    const float* beta  = (const float*)d_in[6];
    const float* fcw   = (const float*)d_in[7];
    const float* fcb   = (const float*)d_in[8];

    const size_t smem_bytes =
        (size_t)(2 * Gn * WPITCH + Gn + RPB * WPITCH + 2 * RPB * Dn + RPB * Gn)
        * sizeof(float);  // 152,032 B < 228 KB cap

    cudaFuncSetAttribute(lstm_kernel,
                         cudaFuncAttributeMaxDynamicSharedMemorySize,
                         (int)smem_bytes);

    lstm_kernel<<<NBLK, NTHR, smem_bytes>>>(x, W_ih, W_hh, b_ih, b_hh);
    bn_fc_kernel<<<1, Bsz>>>(gamma, beta, fcw, fcb, (float*)d_out);
}